// round 2
// baseline (speedup 1.0000x reference)
#include <cuda_runtime.h>
#include <cstdint>
#include <math_constants.h>

// Problem constants (fixed by the dataset)
#define N_PTS   98304      // B*H*W = 96*32*32
#define C_DIM   256
#define HW      1024       // 32*32
#define NSAMP   491
#define NITER   490        // NSAMP - 1
#define NBLK    96         // persistent blocks, all co-resident
#define NTHR    1024       // threads per block; each thread owns 1 point

// Scratch (device globals: no allocation allowed)
__device__ float g_featT[(size_t)C_DIM * N_PTS];          // [C][N], ~100.6 MB
__device__ unsigned long long g_bmax[2][NBLK];            // double-buffered block maxima
__device__ int g_sel[NSAMP];                              // selected indices
__device__ volatile unsigned g_bar;                       // grid barrier counter

// ---------------------------------------------------------------------------
// Init: reset barrier, transpose [B,C,H,W] -> featT[c*N + b*HW + hw]
// ---------------------------------------------------------------------------
__global__ void k_init(const float* __restrict__ in) {
    if (blockIdx.x == 0 && threadIdx.x == 0) { g_bar = 0; g_sel[0] = 0; }
    const int blk = blockIdx.x;          // == b*256 + c (input is [b][c][hw])
    const int b = blk >> 8;
    const int c = blk & 255;
    const float4* src = reinterpret_cast<const float4*>(in + (size_t)blk * HW);
    float4* dst = reinterpret_cast<float4*>(g_featT + (size_t)c * N_PTS + (size_t)b * HW);
    dst[threadIdx.x] = src[threadIdx.x];
}

// ---------------------------------------------------------------------------
// Persistent farthest-point-sampling kernel.
// 96 blocks x 1024 threads; thread t of block B owns point n = B*1024 + t.
// min_d stays in a register across all 490 iterations.
//
// Distance sum bit-matches the XLA:GPU row-reduction emitter:
//   lane l of a virtual warp accumulates cols {l, l+32, ..., l+224} sequentially,
//   then a shfl_down tree (16,8,4,2,1). No FMA contraction anywhere.
// We simulate the 32 virtual lanes with a 32-register accumulator array.
// ---------------------------------------------------------------------------
__global__ void __launch_bounds__(NTHR, 1) k_fps() {
    __shared__ float sq[C_DIM];                 // query vector broadcast
    __shared__ unsigned long long swarp[NTHR / 32];
    __shared__ int s_q;

    const int tid  = threadIdx.x;
    const int lane = tid & 31;
    const int wid  = tid >> 5;
    const int n    = blockIdx.x * NTHR + tid;

    float mind = CUDART_INF_F;

    // initial query: index 0
    if (tid < C_DIM) sq[tid] = g_featT[(size_t)tid * N_PTS];
    __syncthreads();

    for (int it = 0; it < NITER; ++it) {
        // ---- squared distance, XLA row-reduce order ----
        float p[32];
        #pragma unroll
        for (int l = 0; l < 32; ++l) p[l] = 0.f;

        for (int j = 0; j < 8; ++j) {           // 8 strided passes
            const int cbase = j * 32;
            #pragma unroll
            for (int l = 0; l < 32; ++l) {
                float v = g_featT[(size_t)(cbase + l) * N_PTS + n];
                float d = __fsub_rn(v, sq[cbase + l]);
                p[l] = __fadd_rn(p[l], __fmul_rn(d, d));   // no contraction
            }
        }
        // shfl_down tree: offsets 16,8,4,2,1 (only lanes < off feed the result)
        #pragma unroll
        for (int off = 16; off; off >>= 1) {
            #pragma unroll
            for (int l = 0; l < 16; ++l) {
                if (l < off) p[l] = __fadd_rn(p[l], p[l + off]);
            }
        }
        mind = fminf(mind, __fsqrt_rn(p[0]));

        // ---- argmax, first-index-wins: key = bits(min_d)<<32 | ~idx ----
        unsigned long long best =
            ((unsigned long long)__float_as_uint(mind) << 32) | (unsigned)~n;
        #pragma unroll
        for (int off = 16; off; off >>= 1) {
            unsigned long long o = __shfl_xor_sync(0xffffffffu, best, off);
            if (o > best) best = o;
        }
        if (lane == 0) swarp[wid] = best;
        __syncthreads();

        if (wid == 0) {
            unsigned long long b = swarp[lane];            // 32 warps -> 32 entries
            #pragma unroll
            for (int off = 16; off; off >>= 1) {
                unsigned long long o = __shfl_xor_sync(0xffffffffu, b, off);
                if (o > b) b = o;
            }
            if (lane == 0) {
                // publish block max (double-buffered by iteration parity)
                *(volatile unsigned long long*)&g_bmax[it & 1][blockIdx.x] = b;
                __threadfence();                           // release
                atomicAdd((unsigned*)&g_bar, 1u);
                const unsigned target = (unsigned)NBLK * (unsigned)(it + 1);
                while (g_bar < target) { }                 // grid barrier spin
                __threadfence();                           // acquire
            }
        }
        __syncthreads();

        // ---- every block redundantly reduces the 96 block maxima ----
        if (wid == 0) {
            unsigned long long b = 0;
            for (int j = lane; j < NBLK; j += 32) {
                unsigned long long o = *(volatile unsigned long long*)&g_bmax[it & 1][j];
                if (o > b) b = o;
            }
            #pragma unroll
            for (int off = 16; off; off >>= 1) {
                unsigned long long o = __shfl_xor_sync(0xffffffffu, b, off);
                if (o > b) b = o;
            }
            if (lane == 0) {
                const int q = (int)~(unsigned)b;
                s_q = q;
                if (blockIdx.x == 0) g_sel[it + 1] = q;
            }
        }
        __syncthreads();

        // ---- load next query vector into shared ----
        const int q = s_q;
        if (tid < C_DIM) sq[tid] = g_featT[(size_t)tid * N_PTS + q];
        __syncthreads();
    }
}

// ---------------------------------------------------------------------------
// Gather: out = [sampled feats (491*256) | sampled weights (491) | indices (491)]
// ---------------------------------------------------------------------------
__global__ void k_gather(const float* __restrict__ w, float* __restrict__ out) {
    const int s = blockIdx.x;           // 0..490
    const int idx = g_sel[s];
    out[s * C_DIM + threadIdx.x] = g_featT[(size_t)threadIdx.x * N_PTS + idx];
    if (threadIdx.x == 0) {
        out[NSAMP * C_DIM + s]         = w[idx];
        out[NSAMP * C_DIM + NSAMP + s] = (float)idx;
    }
}

// ---------------------------------------------------------------------------
extern "C" void kernel_launch(void* const* d_in, const int* in_sizes, int n_in,
                              void* d_out, int out_size) {
    const float* features = (const float*)d_in[0];   // [96,256,32,32] f32
    const float* weights  = (const float*)d_in[1];   // [98304] f32
    (void)in_sizes; (void)n_in; (void)out_size;      // num_samples fixed at 491

    k_init<<<(96 * 256), 256>>>(features);
    k_fps<<<NBLK, NTHR>>>();
    k_gather<<<NSAMP, C_DIM>>>(weights, (float*)d_out);
}